// round 4
// baseline (speedup 1.0000x reference)
#include <cuda_runtime.h>
#include <cstdint>

#define N_PTS   32768
#define DIM     256
#define KCODES  1024
#define DECAYF  0.99f
#define OMDECAY 0.01f
#define EPSF    1e-5f

// Output layout (concatenated, float32):
// z_q_st [N,D], vq_loss [1], indices [N], new_embedding [K,D],
// new_cluster_size [K], new_ema_w [K,D]
#define OFF_ZQ    0
#define OFF_LOSS  (N_PTS * DIM)                 // 8388608
#define OFF_IDX   (OFF_LOSS + 1)                // 8388609
#define OFF_EMB   (OFF_IDX + N_PTS)             // 8421377
#define OFF_CS    (OFF_EMB + KCODES * DIM)      // 8683521
#define OFF_EMAW  (OFF_CS + KCODES)             // 8684545

__device__ unsigned long long g_keys[N_PTS];
__device__ float g_enorm[KCODES];
__device__ float g_loss;
__device__ float g_n;

// ---------------------------------------------------------------------------
// Init: new_ema_w = decay*ema_w ; new_cs = decay*ema_cs ; keys = +inf ; loss=0
// ---------------------------------------------------------------------------
__global__ void k_init(const float* __restrict__ ema_cs,
                       const float* __restrict__ ema_w,
                       float* __restrict__ out) {
    int i = blockIdx.x * blockDim.x + threadIdx.x;   // grid covers 262144
    if (i < KCODES * DIM) out[OFF_EMAW + i] = DECAYF * ema_w[i];
    if (i < N_PTS)        g_keys[i] = 0xFFFFFFFFFFFFFFFFULL;
    if (i < KCODES)       out[OFF_CS + i] = DECAYF * ema_cs[i];
    if (i == 0)           g_loss = 0.0f;
}

// ---------------------------------------------------------------------------
// Per-code squared norms, one warp per code
// ---------------------------------------------------------------------------
__global__ void k_norm(const float* __restrict__ emb) {
    int warp = (blockIdx.x * blockDim.x + threadIdx.x) >> 5;
    int lane = threadIdx.x & 31;
    if (warp >= KCODES) return;
    const float4* row = (const float4*)(emb + (size_t)warp * DIM);
    float4 a = row[lane * 2 + 0];
    float4 b = row[lane * 2 + 1];
    float s = a.x*a.x + a.y*a.y + a.z*a.z + a.w*a.w
            + b.x*b.x + b.y*b.y + b.z*b.z + b.w*b.w;
#pragma unroll
    for (int off = 16; off; off >>= 1) s += __shfl_down_sync(0xFFFFFFFFu, s, off);
    if (lane == 0) g_enorm[warp] = s;
}

// ---------------------------------------------------------------------------
// Distance GEMM + fused argmin.
// Grid: (N/64, K/64). Block 256 thr, 4x4 register micro-tile, BK=16.
// dist = ||e||^2 - 2 * x.e  (||x||^2 irrelevant for argmin)
// Packed key atomicMin -> global per-point winner. Deterministic.
// ---------------------------------------------------------------------------
#define BM 64
#define BN 64
#define BK 16

__global__ __launch_bounds__(256) void k_dist(const float* __restrict__ z,
                                              const float* __restrict__ emb) {
    __shared__ float As[BK][BM];
    __shared__ float Bs[BK][BN];

    int tid = threadIdx.x;
    int tx = tid & 15;        // code dir
    int ty = tid >> 4;        // point dir
    int m0 = blockIdx.x * BM;
    int n0 = blockIdx.y * BN;

    float acc[4][4] = {};

    // global load mapping: thread -> (row 0..63, 4 consecutive d of 16)
    int lr = tid >> 2;
    int lc = (tid & 3) * 4;
    const float* zrow = z   + (size_t)(m0 + lr) * DIM;
    const float* erow = emb + (size_t)(n0 + lr) * DIM;

    for (int kk = 0; kk < DIM; kk += BK) {
        float4 av = *(const float4*)(zrow + kk + lc);
        float4 bv = *(const float4*)(erow + kk + lc);
        __syncthreads();
        As[lc + 0][lr] = av.x; As[lc + 1][lr] = av.y;
        As[lc + 2][lr] = av.z; As[lc + 3][lr] = av.w;
        Bs[lc + 0][lr] = bv.x; Bs[lc + 1][lr] = bv.y;
        Bs[lc + 2][lr] = bv.z; Bs[lc + 3][lr] = bv.w;
        __syncthreads();
#pragma unroll
        for (int k = 0; k < BK; k++) {
            float4 af = *(const float4*)(&As[k][ty * 4]);
            float4 bf = *(const float4*)(&Bs[k][tx * 4]);
            acc[0][0] += af.x * bf.x; acc[0][1] += af.x * bf.y;
            acc[0][2] += af.x * bf.z; acc[0][3] += af.x * bf.w;
            acc[1][0] += af.y * bf.x; acc[1][1] += af.y * bf.y;
            acc[1][2] += af.y * bf.z; acc[1][3] += af.y * bf.w;
            acc[2][0] += af.z * bf.x; acc[2][1] += af.z * bf.y;
            acc[2][2] += af.z * bf.z; acc[2][3] += af.z * bf.w;
            acc[3][0] += af.w * bf.x; acc[3][1] += af.w * bf.y;
            acc[3][2] += af.w * bf.z; acc[3][3] += af.w * bf.w;
        }
    }

    // epilogue: per-point min over this block's 64 codes, then global atomicMin
    float en[4];
#pragma unroll
    for (int j = 0; j < 4; j++) en[j] = g_enorm[n0 + tx * 4 + j];

#pragma unroll
    for (int i = 0; i < 4; i++) {
        unsigned long long best = 0xFFFFFFFFFFFFFFFFULL;
#pragma unroll
        for (int j = 0; j < 4; j++) {
            int c = n0 + tx * 4 + j;
            float d = en[j] - 2.0f * acc[i][j];
            unsigned int bits = __float_as_uint(d);
            unsigned int u = (bits & 0x80000000u) ? ~bits : (bits | 0x80000000u);
            unsigned long long key = ((unsigned long long)u << 32) | (unsigned int)c;
            if (key < best) best = key;
        }
        // reduce across the 16 threads sharing this point-row
#pragma unroll
        for (int off = 8; off; off >>= 1) {
            unsigned long long o = __shfl_down_sync(0xFFFFFFFFu, best, off, 16);
            if (o < best) best = o;
        }
        if (tx == 0) atomicMin(&g_keys[m0 + ty * 4 + i], best);
    }
}

// ---------------------------------------------------------------------------
// Gather z_q, write indices, accumulate loss + EMA scatter.
// One warp per point; 8 warps / block.
// ---------------------------------------------------------------------------
__global__ __launch_bounds__(256) void k_gather(const float* __restrict__ z,
                                                const float* __restrict__ emb,
                                                float* __restrict__ out) {
    __shared__ float warp_loss[8];
    int wip = threadIdx.x >> 5;          // warp in block
    int lane = threadIdx.x & 31;
    int n = blockIdx.x * 8 + wip;

    float lsum = 0.0f;
    if (n < N_PTS) {
        int k = (int)(g_keys[n] & 0xFFFFFFFFULL);
        const float4* zr = (const float4*)(z   + (size_t)n * DIM);
        const float4* er = (const float4*)(emb + (size_t)k * DIM);
        float4* zq = (float4*)(out + OFF_ZQ + (size_t)n * DIM);
        float* emaw = out + OFF_EMAW + (size_t)k * DIM;
#pragma unroll
        for (int j = 0; j < 2; j++) {
            int i4 = lane * 2 + j;
            float4 zv = zr[i4];
            float4 ev = er[i4];
            zq[i4] = ev;   // z_q_st == z_q numerically
            float dx = zv.x - ev.x, dy = zv.y - ev.y;
            float dz = zv.z - ev.z, dw = zv.w - ev.w;
            lsum += dx*dx + dy*dy + dz*dz + dw*dw;
            int d = i4 * 4;
            atomicAdd(emaw + d + 0, OMDECAY * zv.x);
            atomicAdd(emaw + d + 1, OMDECAY * zv.y);
            atomicAdd(emaw + d + 2, OMDECAY * zv.z);
            atomicAdd(emaw + d + 3, OMDECAY * zv.w);
        }
#pragma unroll
        for (int off = 16; off; off >>= 1)
            lsum += __shfl_down_sync(0xFFFFFFFFu, lsum, off);
        if (lane == 0) {
            atomicAdd(out + OFF_CS + k, OMDECAY);
            out[OFF_IDX + n] = (float)k;
        }
    }
    if (lane == 0) warp_loss[wip] = lsum;
    __syncthreads();
    if (threadIdx.x == 0) {
        float s = 0.0f;
#pragma unroll
        for (int w = 0; w < 8; w++) s += warp_loss[w];
        atomicAdd(&g_loss, s);
    }
}

// ---------------------------------------------------------------------------
// n = sum(new_cluster_size)  (single block of 1024)
// ---------------------------------------------------------------------------
__global__ void k_nsum(const float* __restrict__ out) {
    __shared__ float sh[32];
    int t = threadIdx.x;
    float v = out[OFF_CS + t];
#pragma unroll
    for (int off = 16; off; off >>= 1) v += __shfl_down_sync(0xFFFFFFFFu, v, off);
    if ((t & 31) == 0) sh[t >> 5] = v;
    __syncthreads();
    if (t < 32) {
        float s = sh[t];
#pragma unroll
        for (int off = 16; off; off >>= 1) s += __shfl_down_sync(0xFFFFFFFFu, s, off);
        if (t == 0) g_n = s;
    }
}

// ---------------------------------------------------------------------------
// Finalize: new_embedding = new_ema_w / laplace_smoothed_cs ; write loss
// ---------------------------------------------------------------------------
__global__ void k_final(float* __restrict__ out) {
    int i = blockIdx.x * blockDim.x + threadIdx.x;   // < 262144
    float n = g_n;
    int k = i >> 8;
    float cs = (out[OFF_CS + k] + EPSF) / (n + (float)KCODES * EPSF) * n;
    out[OFF_EMB + i] = out[OFF_EMAW + i] / cs;
    if (i == 0)
        out[OFF_LOSS] = 1.25f * g_loss / (float)(N_PTS * DIM);
}

// ---------------------------------------------------------------------------
extern "C" void kernel_launch(void* const* d_in, const int* in_sizes, int n_in,
                              void* d_out, int out_size) {
    const float* z      = (const float*)d_in[0];  // [32,32,32,256]
    const float* emb    = (const float*)d_in[1];  // [1024,256]
    const float* ema_cs = (const float*)d_in[2];  // [1024]
    const float* ema_w  = (const float*)d_in[3];  // [1024,256]
    float* out = (float*)d_out;

    k_init<<<(KCODES * DIM + 255) / 256, 256>>>(ema_cs, ema_w, out);
    k_norm<<<(KCODES * 32) / 256, 256>>>(emb);
    dim3 gdist(N_PTS / BM, KCODES / BN);
    k_dist<<<gdist, 256>>>(z, emb);
    k_gather<<<N_PTS / 8, 256>>>(z, emb, out);
    k_nsum<<<1, 1024>>>(out);
    k_final<<<(KCODES * DIM + 255) / 256, 256>>>(out);
}

// round 9
// speedup vs baseline: 2.9433x; 2.9433x over previous
#include <cuda_runtime.h>
#include <cuda_fp16.h>
#include <cstdint>

#define N_PTS   32768
#define DIM     256
#define KCODES  1024
#define DECAYF  0.99f
#define OMDECAY 0.01f
#define EPSF    1e-5f
#define MARGIN  2.0f

// Output layout (concatenated, float32)
#define OFF_ZQ    0
#define OFF_LOSS  (N_PTS * DIM)
#define OFF_IDX   (OFF_LOSS + 1)
#define OFF_EMB   (OFF_IDX + N_PTS)
#define OFF_CS    (OFF_EMB + KCODES * DIM)
#define OFF_EMAW  (OFF_CS + KCODES)

__device__ float  g_enorm[KCODES];
__device__ float  g_loss;
__device__ float  g_n;
__device__ __half g_zh[N_PTS * DIM];        // fp16 z
__device__ __half g_eh[KCODES * DIM];       // fp16 embedding
__device__ __half g_dist[N_PTS * KCODES];   // approx distances (67MB)
__device__ int    g_sel[N_PTS];             // chosen code per point
__device__ int    g_cnt[KCODES];
__device__ int    g_off[KCODES];
__device__ int    g_fill[KCODES];
__device__ int    g_bkt[N_PTS];

// ---------------------------------------------------------------------------
// helpers
// ---------------------------------------------------------------------------
__device__ __forceinline__ uint32_t smem_u32(const void* p) {
    uint32_t a;
    asm("{ .reg .u64 t; cvta.to.shared.u64 t, %1; cvt.u32.u64 %0, t; }"
        : "=r"(a) : "l"(p));
    return a;
}
__device__ __forceinline__ void cp16(uint32_t dst, const void* src) {
    asm volatile("cp.async.cg.shared.global [%0], [%1], 16;"
                 :: "r"(dst), "l"(__cvta_generic_to_global(src)) : "memory");
}
#define CP_COMMIT() asm volatile("cp.async.commit_group;" ::: "memory")

#define LDSM_X4(r0, r1, r2, r3, a) \
    asm volatile("ldmatrix.sync.aligned.m8n8.x4.shared.b16 {%0,%1,%2,%3}, [%4];" \
                 : "=r"(r0), "=r"(r1), "=r"(r2), "=r"(r3) : "r"(a))
#define LDSM_X2(r0, r1, a) \
    asm volatile("ldmatrix.sync.aligned.m8n8.x2.shared.b16 {%0,%1}, [%2];" \
                 : "=r"(r0), "=r"(r1) : "r"(a))

__device__ __forceinline__ void mma16816(float* c, const uint32_t* a, const uint32_t* b) {
    asm volatile("mma.sync.aligned.m16n8k16.row.col.f32.f16.f16.f32 "
                 "{%0,%1,%2,%3}, {%4,%5,%6,%7}, {%8,%9}, {%0,%1,%2,%3};"
                 : "+f"(c[0]), "+f"(c[1]), "+f"(c[2]), "+f"(c[3])
                 : "r"(a[0]), "r"(a[1]), "r"(a[2]), "r"(a[3]), "r"(b[0]), "r"(b[1]));
}

// ---------------------------------------------------------------------------
// k_prep: fp32 -> fp16 operands; zero counters
// ---------------------------------------------------------------------------
__global__ void k_prep(const float* __restrict__ z, const float* __restrict__ e) {
    int i = blockIdx.x * blockDim.x + threadIdx.x;
    g_zh[i] = __float2half_rn(z[i]);
    if (i < KCODES * DIM) g_eh[i] = __float2half_rn(e[i]);
    if (i < KCODES) { g_cnt[i] = 0; g_fill[i] = 0; }
    if (i == 0) g_loss = 0.0f;
}

__global__ void k_norm(const float* __restrict__ emb) {
    int warp = (blockIdx.x * blockDim.x + threadIdx.x) >> 5;
    int lane = threadIdx.x & 31;
    if (warp >= KCODES) return;
    const float4* row = (const float4*)(emb + (size_t)warp * DIM);
    float4 a = row[lane * 2 + 0];
    float4 b = row[lane * 2 + 1];
    float s = a.x*a.x + a.y*a.y + a.z*a.z + a.w*a.w
            + b.x*b.x + b.y*b.y + b.z*b.z + b.w*b.w;
#pragma unroll
    for (int off = 16; off; off >>= 1) s += __shfl_down_sync(0xFFFFFFFFu, s, off);
    if (lane == 0) g_enorm[warp] = s;
}

// ---------------------------------------------------------------------------
// HMMA fp16 distance GEMM: D[m][n] = ||e_n||^2 - 2 * z_m . e_n  (approx, fp16 out)
// BM=128, BN=128, BK=64 halves. 8 warps: warp_m = wid&1 (64 rows), warp_n = wid>>1 (32 cols)
// smem rows padded to 144B so ldmatrix rows land on distinct banks.
// ---------------------------------------------------------------------------
#define ROWB    144                      // 64 halves data + 8 pad = 144 bytes
#define EN_OFF  0
#define ST_A(s) (512 + (s) * 36864)
#define ST_B(s) (512 + (s) * 36864 + 18432)
#define SMEM_SZ (512 + 2 * 36864)        // 74240

__device__ __forceinline__ void load_stage(uint32_t sb, int s, int m0, int n0,
                                           int kk, int tid) {
#pragma unroll
    for (int i = 0; i < 4; i++) {
        int ch = tid + i * 256;          // 1024 chunks of 16B
        int r = ch >> 3, sg = ch & 7;
        uint32_t o = (uint32_t)(r * ROWB + sg * 16);
        cp16(sb + ST_A(s) + o, g_zh + (size_t)(m0 + r) * DIM + kk + sg * 8);
        cp16(sb + ST_B(s) + o, g_eh + (size_t)(n0 + r) * DIM + kk + sg * 8);
    }
}

__global__ __launch_bounds__(256, 2) void k_dist_hmma() {
    extern __shared__ char smem[];
    uint32_t sb = smem_u32(smem);
    int tid = threadIdx.x;
    int wid = tid >> 5;
    int lane = tid & 31;
    int n0 = blockIdx.x * 128;
    int m0 = blockIdx.y * 128;
    int warp_m = wid & 1;                // 2 tiles of 64 rows
    int warp_n = wid >> 1;               // 4 tiles of 32 cols

    if (tid < 128) ((float*)(smem + EN_OFF))[tid] = g_enorm[n0 + tid];

    float acc[4][4][4] = {};             // [mi 16][nj 8][frag]

    // per-lane ldmatrix address invariants
    int rA = warp_m * 64 + (lane & 7) + (((lane >> 3) & 1) << 3);
    int cA8 = ((lane >> 4) & 1) << 3;
    int rB = warp_n * 32 + (lane & 7);
    int cB8 = ((lane >> 3) & 1) << 3;

    load_stage(sb, 0, m0, n0, 0, tid); CP_COMMIT();
    load_stage(sb, 1, m0, n0, 64, tid); CP_COMMIT();

    for (int c = 0; c < 4; c++) {
        int s = c & 1;
        if (c < 3) asm volatile("cp.async.wait_group 1;" ::: "memory");
        else       asm volatile("cp.async.wait_group 0;" ::: "memory");
        __syncthreads();

#pragma unroll
        for (int ks = 0; ks < 4; ks++) {
            int k0 = ks * 16;
            uint32_t a[4][4], b[4][2];
#pragma unroll
            for (int mi = 0; mi < 4; mi++) {
                uint32_t ad = sb + ST_A(s) + (rA + mi * 16) * ROWB + (k0 + cA8) * 2;
                LDSM_X4(a[mi][0], a[mi][1], a[mi][2], a[mi][3], ad);
            }
#pragma unroll
            for (int nj = 0; nj < 4; nj++) {
                uint32_t bd = sb + ST_B(s) + (rB + nj * 8) * ROWB + (k0 + cB8) * 2;
                LDSM_X2(b[nj][0], b[nj][1], bd);
            }
#pragma unroll
            for (int mi = 0; mi < 4; mi++)
#pragma unroll
                for (int nj = 0; nj < 4; nj++)
                    mma16816(acc[mi][nj], a[mi], b[nj]);
        }
        __syncthreads();
        if (c + 2 < 4) { load_stage(sb, s, m0, n0, (c + 2) * 64, tid); CP_COMMIT(); }
    }

    // epilogue: dist = en - 2*acc, store fp16
    const float* en = (const float*)(smem + EN_OFF);
#pragma unroll
    for (int mi = 0; mi < 4; mi++) {
#pragma unroll
        for (int nj = 0; nj < 4; nj++) {
            int cw = warp_n * 32 + nj * 8 + (lane & 3) * 2;
            int r0 = m0 + warp_m * 64 + mi * 16 + (lane >> 2);
            float e0 = en[cw], e1 = en[cw + 1];
            __half2 v0 = __floats2half2_rn(e0 - 2.0f * acc[mi][nj][0],
                                           e1 - 2.0f * acc[mi][nj][1]);
            __half2 v1 = __floats2half2_rn(e0 - 2.0f * acc[mi][nj][2],
                                           e1 - 2.0f * acc[mi][nj][3]);
            *(__half2*)(g_dist + (size_t)r0 * KCODES + n0 + cw) = v0;
            *(__half2*)(g_dist + (size_t)(r0 + 8) * KCODES + n0 + cw) = v1;
        }
    }
}

// ---------------------------------------------------------------------------
// k_select: warp per point. Approx min over 1024, candidates within MARGIN,
// exact fp32 rescore, lowest-index tiebreak. Also counts per-code membership.
// ---------------------------------------------------------------------------
__global__ __launch_bounds__(256) void k_select(const float* __restrict__ z,
                                                const float* __restrict__ emb) {
    __shared__ int s_cnt[8];
    __shared__ int s_list[8][128];
    int w = threadIdx.x >> 5;
    int lane = threadIdx.x & 31;
    int n = blockIdx.x * 8 + w;

    if (lane == 0) s_cnt[w] = 0;
    __syncwarp();

    const uint4* rowp = (const uint4*)(g_dist + (size_t)n * KCODES);
    uint4 u[4];
    float vmin = 3.4e38f;
#pragma unroll
    for (int i = 0; i < 4; i++) {
        u[i] = rowp[lane + 32 * i];
        const uint32_t* ww = (const uint32_t*)&u[i];
#pragma unroll
        for (int j = 0; j < 4; j++) {
            float2 f = __half22float2(*(const __half2*)&ww[j]);
            vmin = fminf(vmin, fminf(f.x, f.y));
        }
    }
#pragma unroll
    for (int off = 16; off; off >>= 1)
        vmin = fminf(vmin, __shfl_xor_sync(0xFFFFFFFFu, vmin, off));
    float thr = vmin + MARGIN;

#pragma unroll
    for (int i = 0; i < 4; i++) {
        const uint32_t* ww = (const uint32_t*)&u[i];
#pragma unroll
        for (int j = 0; j < 4; j++) {
            float2 f = __half22float2(*(const __half2*)&ww[j]);
            int c0 = (lane + 32 * i) * 8 + j * 2;
            if (f.x <= thr) { int p = atomicAdd(&s_cnt[w], 1); if (p < 128) s_list[w][p] = c0; }
            if (f.y <= thr) { int p = atomicAdd(&s_cnt[w], 1); if (p < 128) s_list[w][p] = c0 + 1; }
        }
    }
    __syncwarp();
    int cnt = min(s_cnt[w], 128);

    // preload z row (8 floats/lane)
    const float4* zr = (const float4*)(z + (size_t)n * DIM);
    float4 za = zr[lane * 2], zb = zr[lane * 2 + 1];

    float bd = 3.4e38f;
    int bc = 0x7FFFFFFF;
    for (int t = 0; t < cnt; t++) {
        int c = s_list[w][t];
        const float4* er = (const float4*)(emb + (size_t)c * DIM);
        float4 ea = er[lane * 2], eb = er[lane * 2 + 1];
        float s = za.x*ea.x + za.y*ea.y + za.z*ea.z + za.w*ea.w
                + zb.x*eb.x + zb.y*eb.y + zb.z*eb.z + zb.w*eb.w;
#pragma unroll
        for (int off = 16; off; off >>= 1)
            s += __shfl_xor_sync(0xFFFFFFFFu, s, off);
        float d = g_enorm[c] - 2.0f * s;
        if (d < bd || (d == bd && c < bc)) { bd = d; bc = c; }
    }
    if (lane == 0) {
        g_sel[n] = bc;
        atomicAdd(&g_cnt[bc], 1);
    }
}

// ---------------------------------------------------------------------------
// k_gather: z_q write, indices, loss (no global atomics on ema)
// ---------------------------------------------------------------------------
__global__ __launch_bounds__(256) void k_gather(const float* __restrict__ z,
                                                const float* __restrict__ emb,
                                                float* __restrict__ out) {
    __shared__ float warp_loss[8];
    int w = threadIdx.x >> 5;
    int lane = threadIdx.x & 31;
    int n = blockIdx.x * 8 + w;

    int k = g_sel[n];
    const float4* zr = (const float4*)(z   + (size_t)n * DIM);
    const float4* er = (const float4*)(emb + (size_t)k * DIM);
    float4* zq = (float4*)(out + OFF_ZQ + (size_t)n * DIM);
    float lsum = 0.0f;
#pragma unroll
    for (int j = 0; j < 2; j++) {
        int i4 = lane * 2 + j;
        float4 zv = zr[i4];
        float4 ev = er[i4];
        zq[i4] = ev;
        float dx = zv.x - ev.x, dy = zv.y - ev.y;
        float dz = zv.z - ev.z, dw = zv.w - ev.w;
        lsum += dx*dx + dy*dy + dz*dz + dw*dw;
    }
#pragma unroll
    for (int off = 16; off; off >>= 1)
        lsum += __shfl_down_sync(0xFFFFFFFFu, lsum, off);
    if (lane == 0) {
        out[OFF_IDX + n] = (float)k;
        warp_loss[w] = lsum;
    }
    __syncthreads();
    if (threadIdx.x == 0) {
        float s = 0.0f;
#pragma unroll
        for (int i = 0; i < 8; i++) s += warp_loss[i];
        atomicAdd(&g_loss, s);
    }
}

// ---------------------------------------------------------------------------
// k_off: exclusive prefix of counts; write new_cluster_size
// ---------------------------------------------------------------------------
__global__ void k_off(const float* __restrict__ ema_cs, float* __restrict__ out) {
    __shared__ int sh[KCODES];
    int t = threadIdx.x;
    int v = g_cnt[t];
    out[OFF_CS + t] = DECAYF * ema_cs[t] + OMDECAY * (float)v;
    sh[t] = v;
    __syncthreads();
    for (int off = 1; off < KCODES; off <<= 1) {
        int x = (t >= off) ? sh[t - off] : 0;
        __syncthreads();
        sh[t] += x;
        __syncthreads();
    }
    g_off[t] = sh[t] - v;
}

__global__ void k_fill() {
    int n = blockIdx.x * blockDim.x + threadIdx.x;
    int c = g_sel[n];
    int pos = g_off[c] + atomicAdd(&g_fill[c], 1);
    g_bkt[pos] = n;
}

// block per code: dw sum + new_ema_w
__global__ __launch_bounds__(256) void k_dw(const float* __restrict__ z,
                                            const float* __restrict__ ema_w,
                                            float* __restrict__ out) {
    int c = blockIdx.x;
    int d = threadIdx.x;
    int beg = g_off[c], cnt = g_cnt[c];
    float acc = 0.0f;
    for (int m = 0; m < cnt; m++) {
        int p = g_bkt[beg + m];
        acc += z[(size_t)p * DIM + d];
    }
    out[OFF_EMAW + (size_t)c * DIM + d] =
        DECAYF * ema_w[(size_t)c * DIM + d] + OMDECAY * acc;
}

__global__ void k_nsum(const float* __restrict__ out) {
    __shared__ float sh[32];
    int t = threadIdx.x;
    float v = out[OFF_CS + t];
#pragma unroll
    for (int off = 16; off; off >>= 1) v += __shfl_down_sync(0xFFFFFFFFu, v, off);
    if ((t & 31) == 0) sh[t >> 5] = v;
    __syncthreads();
    if (t < 32) {
        float s = sh[t];
#pragma unroll
        for (int off = 16; off; off >>= 1) s += __shfl_down_sync(0xFFFFFFFFu, s, off);
        if (t == 0) g_n = s;
    }
}

__global__ void k_final(float* __restrict__ out) {
    int i = blockIdx.x * blockDim.x + threadIdx.x;
    float n = g_n;
    int k = i >> 8;
    float cs = (out[OFF_CS + k] + EPSF) / (n + (float)KCODES * EPSF) * n;
    out[OFF_EMB + i] = out[OFF_EMAW + i] / cs;
    if (i == 0)
        out[OFF_LOSS] = 1.25f * g_loss / (float)(N_PTS * DIM);
}

// ---------------------------------------------------------------------------
extern "C" void kernel_launch(void* const* d_in, const int* in_sizes, int n_in,
                              void* d_out, int out_size) {
    const float* z      = (const float*)d_in[0];
    const float* emb    = (const float*)d_in[1];
    const float* ema_cs = (const float*)d_in[2];
    const float* ema_w  = (const float*)d_in[3];
    float* out = (float*)d_out;

    cudaFuncSetAttribute(k_dist_hmma,
                         cudaFuncAttributeMaxDynamicSharedMemorySize, SMEM_SZ);

    k_prep<<<(N_PTS * DIM) / 256, 256>>>(z, emb);
    k_norm<<<(KCODES * 32) / 256, 256>>>(emb);
    k_dist_hmma<<<dim3(KCODES / 128, N_PTS / 128), 256, SMEM_SZ>>>();
    k_select<<<N_PTS / 8, 256>>>(z, emb);
    k_gather<<<N_PTS / 8, 256>>>(z, emb, out);
    k_off<<<1, KCODES>>>(ema_cs, out);
    k_fill<<<N_PTS / 256, 256>>>();
    k_dw<<<KCODES, 256>>>(z, ema_w, out);
    k_nsum<<<1, 1024>>>(out);
    k_final<<<(KCODES * DIM) / 256, 256>>>(out);
}